// round 11
// baseline (speedup 1.0000x reference)
#include <cuda_runtime.h>

#define ULL unsigned long long

// ---------- packed f32x2 helpers ----------
__device__ __forceinline__ void fma2(ULL &acc, ULL a, ULL b) {
    asm("fma.rn.f32x2 %0, %1, %2, %0;" : "+l"(acc) : "l"(a), "l"(b));
}
__device__ __forceinline__ ULL add2(ULL a, ULL b) {
    ULL r; asm("add.rn.f32x2 %0, %1, %2;" : "=l"(r) : "l"(a), "l"(b)); return r;
}
__device__ __forceinline__ float2 unpack2(ULL v) {
    float2 r; asm("mov.b64 {%0, %1}, %2;" : "=f"(r.x), "=f"(r.y) : "l"(v)); return r;
}
__device__ __forceinline__ ULL pack2(float x, float y) {
    ULL r; asm("mov.b64 %0, {%1, %2};" : "=l"(r) : "f"(x), "f"(y)); return r;
}

// ---------- problem dims ----------
#define MM 16
#define NN 4096
#define HH 32
#define DD 128
#define PP 8192
#define PTOT (PP + MM)
#define KSPLIT 16
#define PCH 256
#define NPCH 33                 // ceil(8208/256)
#define PSTR (NPCH * PCH)       // 8448

// ---------- device scratch ----------
__device__ float g_invr[MM];
__device__ float g_part[KSPLIT * 3 * MM * NN];
__device__ float g_q[MM * NN];
__device__ float g_k[MM * NN];
__device__ float g_v[MM * NN];
__device__ float g_sexp[HH * PSTR * MM];          // [h][p][m], 17.3MB
__device__ float g_nump[NPCH * HH * MM * DD];
__device__ float g_denp[NPCH * HH * MM];

// ============================================================
// K1: per-row inverse RMS
// ============================================================
__global__ __launch_bounds__(256) void rms_kernel(const float* __restrict__ X) {
    int m = blockIdx.x;
    int t = threadIdx.x;
    float s = 0.f;
    const float4* Xr = (const float4*)(X + m * NN);
    for (int i = t; i < NN / 4; i += 256) {
        float4 v = Xr[i];
        s += v.x * v.x + v.y * v.y + v.z * v.z + v.w * v.w;
    }
    __shared__ float red[8];
    for (int o = 16; o; o >>= 1) s += __shfl_xor_sync(0xffffffffu, s, o);
    if ((t & 31) == 0) red[t >> 5] = s;
    __syncthreads();
    if (t == 0) {
        float tot = 0.f;
        #pragma unroll
        for (int i = 0; i < 8; i++) tot += red[i];
        g_invr[m] = rsqrtf(tot * (1.0f / (float)NN));
    }
}

// ============================================================
// K2: QKV projection, broadcast-operand design. KSPLIT=16.
// grid 1536 = 16 k-splits x (3 weights x 32 j-groups of 128).
// ============================================================
__global__ __launch_bounds__(128) void qkv_kernel(
    const float* __restrict__ X,
    const float* __restrict__ Wq,
    const float* __restrict__ Wk,
    const float* __restrict__ Wv)
{
    __shared__ ULL Wt[2][16][129];
    __shared__ ULL xq[2][MM][16];

    int bid = blockIdx.x;
    int kh = bid / 96;                 // k-split 0..15
    int g  = bid % 96;
    int wsel  = g >> 5;
    int jbase = (g & 31) << 7;
    const float* W = (wsel == 0) ? Wq : (wsel == 1) ? Wk : Wv;
    int koff = kh << 8;                // *256

    int t = threadIdx.x;
    int jrow = t >> 3, cq = t & 7;

    float4 wr[8];
    #pragma unroll
    for (int i = 0; i < 8; i++)
        wr[i] = *(const float4*)(W + (size_t)(jbase + jrow + 16 * i) * NN + koff + cq * 4);
    float iv = g_invr[jrow];
    float4 xr = *(const float4*)(X + jrow * NN + koff + cq * 4);
    xr.x *= iv; xr.y *= iv; xr.z *= iv; xr.w *= iv;

    ULL acc[MM];
    #pragma unroll
    for (int m = 0; m < MM; m++) acc[m] = 0ull;

    for (int kc = 0; kc < 8; kc++) {
        int buf = kc & 1;
        #pragma unroll
        for (int i = 0; i < 8; i++) {
            Wt[buf][2 * cq][jrow + 16 * i]     = pack2(wr[i].x, wr[i].y);
            Wt[buf][2 * cq + 1][jrow + 16 * i] = pack2(wr[i].z, wr[i].w);
        }
        *(float4*)&xq[buf][jrow][2 * cq] = xr;
        __syncthreads();

        if (kc < 7) {
            int kb = koff + (kc + 1) * 32;
            #pragma unroll
            for (int i = 0; i < 8; i++)
                wr[i] = *(const float4*)(W + (size_t)(jbase + jrow + 16 * i) * NN + kb + cq * 4);
            xr = *(const float4*)(X + jrow * NN + kb + cq * 4);
            xr.x *= iv; xr.y *= iv; xr.z *= iv; xr.w *= iv;
        }

        #pragma unroll
        for (int kpp = 0; kpp < 8; kpp++) {
            ULL w0 = Wt[buf][2 * kpp][t];
            ULL w1 = Wt[buf][2 * kpp + 1][t];
            #pragma unroll
            for (int m = 0; m < MM; m++) {
                ulonglong2 xv = *(const ulonglong2*)&xq[buf][m][2 * kpp];
                fma2(acc[m], w0, xv.x);
                fma2(acc[m], w1, xv.y);
            }
        }
    }

    float* dst = g_part + ((size_t)kh * 3 + wsel) * (MM * NN);
    #pragma unroll
    for (int m = 0; m < MM; m++) {
        float2 f = unpack2(acc[m]);
        dst[m * NN + jbase + t] = f.x + f.y;
    }
}

// ============================================================
// K2b: combine k-split partials -> g_q / g_k / g_v
// ============================================================
__global__ __launch_bounds__(256) void combine_kernel() {
    int idx = blockIdx.x * 256 + threadIdx.x;
    int sel = idx >> 16, r = idx & 65535;
    float v = 0.f;
    #pragma unroll
    for (int c = 0; c < KSPLIT; c++)
        v += g_part[((size_t)c * 3 + sel) * 65536 + r];
    float* o = (sel == 0) ? g_q : (sel == 1) ? g_k : g_v;
    o[r] = v;
}

// ============================================================
// K3a: score kernel. grid (33, 32), 128 thr.
// Computes exp(q.K) for a 256-p chunk, writes to g_sexp[h][p][m],
// den partials to g_denp. Transpose+overlay structure (proven R7-10).
// ============================================================
__global__ __launch_bounds__(128, 4) void score_kernel(const float* __restrict__ cacheK) {
    __shared__ ULL qs2[MM][64];
    __shared__ ULL Kt[64][32];
    __shared__ float den4[4][16];

    int chunk = blockIdx.x, h = blockIdx.y;
    int t = threadIdx.x, w = t >> 5, lane = t & 31;
    int rm = t & 15, rpg = t >> 4;

    #pragma unroll
    for (int i = 0; i < 4; i++) {
        int idx = t + i * 128;
        int m = idx >> 5, cq = idx & 31;
        float4 v = *(const float4*)(g_q + m * NN + h * DD + cq * 4);
        *(float4*)&qs2[m][2 * cq] = v;
    }

    float den_t = 0.f;
    int ntiles = (chunk < NPCH - 1) ? (PCH / 32) : 1;
    int pbase = chunk * PCH;

    float4 pk[8];
    #pragma unroll
    for (int i = 0; i < 8; i++) {
        int r = w + 4 * i, pg = pbase + r;
        if (pg < PP)
            pk[i] = *(const float4*)(cacheK + ((size_t)h * PP + pg) * DD + lane * 4);
        else if (pg < PTOT)
            pk[i] = *(const float4*)(g_k + (pg - PP) * NN + h * DD + lane * 4);
        else
            pk[i] = make_float4(0.f, 0.f, 0.f, 0.f);
    }

    for (int tile = 0; tile < ntiles; tile++) {
        int p0 = pbase + tile * 32;
        __syncthreads();                       // prev reduce-reads of Kt done
        #pragma unroll
        for (int i = 0; i < 8; i++) {
            int r = w + 4 * i;
            int col = (r ^ lane) & 31;
            Kt[2 * lane][col]     = pack2(pk[i].x, pk[i].y);
            Kt[2 * lane + 1][col] = pack2(pk[i].z, pk[i].w);
        }
        __syncthreads();                       // Kt ready
        if (tile + 1 < ntiles) {               // all-cacheK here (chunk<32)
            #pragma unroll
            for (int i = 0; i < 8; i++) {
                int r = w + 4 * i;
                pk[i] = *(const float4*)(cacheK + ((size_t)h * PP + p0 + 32 + r) * DD + lane * 4);
            }
        }

        // score phase: warp w handles kp in [16w, 16w+16); lane owns p
        ULL as[MM];
        #pragma unroll
        for (int m = 0; m < MM; m++) as[m] = 0ull;
        #pragma unroll
        for (int kpp = 0; kpp < 8; kpp++) {
            int kpA = w * 16 + 2 * kpp;
            int col = (lane ^ (kpA >> 1)) & 31;
            ULL kA = Kt[kpA][col];
            ULL kB = Kt[kpA + 1][col];
            #pragma unroll
            for (int m = 0; m < MM; m++) {
                ulonglong2 qv = *(const ulonglong2*)&qs2[m][kpA];
                fma2(as[m], kA, qv.x);
                fma2(as[m], kB, qv.y);
            }
        }
        // overlay partials into this warp's OWN Kt rows (only it read them)
        #pragma unroll
        for (int m = 0; m < MM; m++)
            Kt[w * 16 + m][(lane ^ m) & 31] = as[m];
        __syncthreads();

        // reduce -> exp -> global (coalesced [p][m] runs)
        #pragma unroll
        for (int i = 0; i < 4; i++) {
            int p = rpg * 4 + i;
            int col = (p ^ rm) & 31;
            ULL ssum = add2(add2(Kt[rm][col],      Kt[16 + rm][col]),
                            add2(Kt[32 + rm][col], Kt[48 + rm][col]));
            float2 f = unpack2(ssum);
            float e = ((p0 + p) < PTOT) ? __expf(f.x + f.y) : 0.f;
            den_t += e;
            g_sexp[((size_t)h * PSTR + p0 + p) * MM + rm] = e;
        }
    }

    den_t += __shfl_xor_sync(0xffffffffu, den_t, 16);
    if (lane < 16) den4[w][lane] = den_t;
    __syncthreads();
    if (t < 16)
        g_denp[(chunk * HH + h) * MM + t] =
            den4[0][t] + den4[1][t] + den4[2][t] + den4[3][t];
}

// ============================================================
// K3b: O kernel. grid (33, 32), 128 thr. No K, no per-tile barriers.
// Scores staged once (pre-duplicated f32x2); V rows stream gmem->regs,
// each feeding 16 fma2. Warp (pg2,mg) covers 128 p x 8 m; lane owns d.
// ============================================================
__global__ __launch_bounds__(128, 5) void attno_kernel(const float* __restrict__ cacheV) {
    __shared__ ULL es2[PCH][MM];       // duplicated-pair scores, 32KB
    __shared__ ULL ox[MM * 32 * 2];    // cross-warp exchange, 8KB

    int chunk = blockIdx.x, h = blockIdx.y;
    int t = threadIdx.x, w = t >> 5, lane = t & 31;
    int pg2 = w & 1, mg = w >> 1;
    int pbase = chunk * PCH;

    // stage + duplicate scores: 4096 floats -> 4096 ULL
    {
        const float* src = g_sexp + ((size_t)h * PSTR + pbase) * MM;
        ULL* e2 = &es2[0][0];
        #pragma unroll
        for (int i = 0; i < 8; i++) {
            int idx = i * 128 + t;
            float4 v = *(const float4*)(src + idx * 4);
            e2[idx * 4 + 0] = pack2(v.x, v.x);
            e2[idx * 4 + 1] = pack2(v.y, v.y);
            e2[idx * 4 + 2] = pack2(v.z, v.z);
            e2[idx * 4 + 3] = pack2(v.w, v.w);
        }
    }
    __syncthreads();

    ULL oa[16];
    #pragma unroll
    for (int i = 0; i < 16; i++) oa[i] = 0ull;

    int npw = (chunk < NPCH - 1) ? 128 : (pg2 ? 0 : 16);
    const float* vrow;
    size_t vstep;
    if (pbase < PP) {   // chunk < 32: all rows from cache
        vrow = cacheV + ((size_t)h * PP + pbase + pg2 * 128) * DD + lane * 4;
        vstep = DD;
    } else {            // chunk 32: all rows from g_v (pg2=0 only)
        vrow = g_v + (size_t)(pbase - PP) * NN + h * DD + lane * 4;
        vstep = NN;
    }

    #pragma unroll 4
    for (int pp = 0; pp < npw; pp++) {
        int p = pg2 * 128 + pp;
        ulonglong2 vv = *(const ulonglong2*)(vrow + (size_t)pp * vstep);
        #pragma unroll
        for (int mi = 0; mi < 8; mi++) {
            ULL sa = es2[p][mg * 8 + mi];      // LDS.64 broadcast
            fma2(oa[2 * mi],     vv.x, sa);
            fma2(oa[2 * mi + 1], vv.y, sa);
        }
    }

    // cross-warp p-half reduction
    if (pg2 == 1) {
        #pragma unroll
        for (int mi = 0; mi < 8; mi++) {
            ulonglong2 v;
            v.x = oa[2 * mi]; v.y = oa[2 * mi + 1];
            *(ulonglong2*)&ox[((mg * 8 + mi) * 32 + lane) * 2] = v;
        }
    }
    __syncthreads();
    if (pg2 == 0) {
        float* np = g_nump + (((size_t)chunk * HH + h) * MM + mg * 8) * DD + lane * 4;
        #pragma unroll
        for (int mi = 0; mi < 8; mi++) {
            ulonglong2 pv = *(const ulonglong2*)&ox[((mg * 8 + mi) * 32 + lane) * 2];
            ULL r0 = add2(oa[2 * mi], pv.x);
            ULL r1 = add2(oa[2 * mi + 1], pv.y);
            float2 lo = unpack2(r0), hi = unpack2(r1);
            *(float4*)(np + mi * DD) = make_float4(lo.x, lo.y, hi.x, hi.y);
        }
    }
}

// ============================================================
// K4: combine partials, divide, write output [M, N]
// ============================================================
__global__ __launch_bounds__(256) void final_kernel(float* __restrict__ out) {
    int idx = blockIdx.x * 256 + threadIdx.x;
    int m = idx >> 12;
    int hd = idx & 4095;
    int h = hd >> 7, d = hd & 127;
    float num = 0.f, den = 0.f;
    #pragma unroll
    for (int c = 0; c < NPCH; c++) {
        num += g_nump[(((size_t)c * HH + h) * MM + m) * DD + d];
        den += g_denp[(c * HH + h) * MM + m];
    }
    out[idx] = num / den;
}

// ============================================================
extern "C" void kernel_launch(void* const* d_in, const int* in_sizes, int n_in,
                              void* d_out, int out_size) {
    const float* X  = (const float*)d_in[0];
    const float* Wq = (const float*)d_in[1];
    const float* Wk = (const float*)d_in[2];
    const float* Wv = (const float*)d_in[3];
    const float* cK = (const float*)d_in[4];
    const float* cV = (const float*)d_in[5];
    float* out = (float*)d_out;

    rms_kernel<<<MM, 256>>>(X);
    qkv_kernel<<<1536, 128>>>(X, Wq, Wk, Wv);
    combine_kernel<<<768, 256>>>();
    score_kernel<<<dim3(NPCH, HH, 1), 128>>>(cK);
    attno_kernel<<<dim3(NPCH, HH, 1), 128>>>(cV);
    final_kernel<<<(MM * NN) / 256, 256>>>(out);
}